// round 16
// baseline (speedup 1.0000x reference)
// QLSTM: quantum-gate LSTM, T=2048, B=256, D=128, H=NQ=4.
//
// Kernel 1 (qlstm_gemm) v5: ROW-OWNER, DIRECT-LDG. Lane owns one row and
//   loads its row chunk (128B-aligned line) straight into registers -> no x
//   smem, no STS, no syncwarp. W via broadcast LDS.128 (lane-uniform).
//   Per k: 4 LDS + 1 pk2 + 8 fma2. 256-thread blocks; load latency hidden
//   by occupancy instead of software pipelining.
//
// Kernel 2 (qlstm_scan): sequence-parallel, CHUNK=32, BURN=64.
//   f = sigmoid(p), p in [-1,1] -> contraction <= 0.731/step. BURN=96 was
//   bit-exact => rho^64 residual ~1e-5, far under the 1e-3 gate. Serial
//   wall = 96 steps. Per-step: quad layout + butterfly transpose, 4-deep
//   register prefetch ring, MUFU.TANH gates, ex2+rcp tanh(c).

#include <cuda_runtime.h>
#include <cstdint>

#define TT 2048
#define BB 256
#define DD 128
#define ROWS (TT * BB)   // 524288
#define CHUNK 32
#define NCHUNK (TT / CHUNK)   // 64
#define BURN 64

// scratch: pre-activations [T][B][16] + 4 timesteps padding (ring overrun)
__device__ __align__(128) float g_pre[(TT + 4) * BB * 16];

// ---------------------------------------------------------------------------
// math helpers
// ---------------------------------------------------------------------------
__device__ __forceinline__ float tanh_hw(float x) {          // MUFU.TANH
    float r;
    asm("tanh.approx.f32 %0, %1;" : "=f"(r) : "f"(x));
    return r;
}
__device__ __forceinline__ float rcp_fast(float x) {         // MUFU.RCP
    float r;
    asm("rcp.approx.f32 %0, %1;" : "=f"(r) : "f"(x));
    return r;
}
__device__ __forceinline__ float ex2_fast(float x) {         // MUFU.EX2
    float r;
    asm("ex2.approx.f32 %0, %1;" : "=f"(r) : "f"(x));
    return r;
}
// precise tanh via exp2: tanh(x) = 1 - 2/(1 + e^{2x}); |x| <= ~2.8 here.
__device__ __forceinline__ float tanh_exp(float x) {
    float e = ex2_fast(x * 2.8853900817779268f);  // 2*log2(e)
    float r = rcp_fast(e + 1.0f);
    return fmaf(-2.0f, r, 1.0f);
}

// f32x2 packed helpers (Blackwell)
typedef unsigned long long u64;
__device__ __forceinline__ u64 pk2(float lo, float hi) {
    u64 r;
    asm("mov.b64 %0, {%1, %2};" : "=l"(r) : "f"(lo), "f"(hi));
    return r;
}
__device__ __forceinline__ void upk2(u64 v, float& lo, float& hi) {
    asm("mov.b64 {%0, %1}, %2;" : "=f"(lo), "=f"(hi) : "l"(v));
}
__device__ __forceinline__ u64 fma2(u64 a, u64 b, u64 c) {
    u64 d;
    asm("fma.rn.f32x2 %0, %1, %2, %3;" : "=l"(d) : "l"(a), "l"(b), "l"(c));
    return d;
}

// ---------------------------------------------------------------------------
// Kernel 1 v5: 256 threads/block, 256 rows/block, 1 row per lane, direct LDG.
// ---------------------------------------------------------------------------
__global__ __launch_bounds__(256) void qlstm_gemm(
    const float* __restrict__ x,
    const float* __restrict__ W0, const float* __restrict__ b0, const float* __restrict__ q0,
    const float* __restrict__ W1, const float* __restrict__ b1, const float* __restrict__ q1,
    const float* __restrict__ W2, const float* __restrict__ b2, const float* __restrict__ q2,
    const float* __restrict__ W3, const float* __restrict__ b3, const float* __restrict__ q3)
{
    __shared__ __align__(16) float ws[128 * 16];   // combined W [k][g*4+q]
    __shared__ float bt[16];

    int tid = (int)threadIdx.x;

    // stage combined W + bias/theta (once per block)
    for (int idx = tid; idx < 2048; idx += 256) {
        int j = idx >> 4, c = idx & 15, gg = c >> 2, k = c & 3;
        const float* W = (gg == 0) ? W0 : (gg == 1) ? W1 : (gg == 2) ? W2 : W3;
        ws[j * 16 + c] = W[j * 4 + k];
    }
    if (tid < 16) {
        int gg = tid >> 2, k = tid & 3;
        const float* bb = (gg == 0) ? b0 : (gg == 1) ? b1 : (gg == 2) ? b2 : b3;
        const float* qq = (gg == 0) ? q0 : (gg == 1) ? q1 : (gg == 2) ? q2 : q3;
        bt[tid] = bb[k] + qq[k];
    }
    __syncthreads();

    size_t row = (size_t)blockIdx.x * 256 + tid;          // lane's row
    const float4* xin4 = (const float4*)x + row * 32;     // 32 float4 per row

    u64 acc[8];
    #pragma unroll
    for (int p = 0; p < 8; p++)
        acc[p] = pk2(bt[2 * p], bt[2 * p + 1]);

    #pragma unroll 1
    for (int c = 0; c < 4; c++) {
        // lane's chunk: 8 float4 = one 128B-aligned line -> sector-clean
        float4 xv[8];
        #pragma unroll
        for (int j = 0; j < 8; j++)
            xv[j] = xin4[c * 8 + j];

        const float* wsc = &ws[(c * 32) * 16];
        #pragma unroll
        for (int k = 0; k < 32; k++) {
            const ulonglong2* wp = (const ulonglong2*)&wsc[k * 16];
            ulonglong2 wa = wp[0];   // broadcast (lane-uniform address)
            ulonglong2 wb = wp[1];
            ulonglong2 wc2 = wp[2];
            ulonglong2 wd = wp[3];
            float4 q = xv[k >> 2];
            float xs_ = ((k & 3) == 0) ? q.x : ((k & 3) == 1) ? q.y
                      : ((k & 3) == 2) ? q.z : q.w;       // folds post-unroll
            u64 xp = pk2(xs_, xs_);
            acc[0] = fma2(xp, wa.x, acc[0]);
            acc[1] = fma2(xp, wa.y, acc[1]);
            acc[2] = fma2(xp, wb.x, acc[2]);
            acc[3] = fma2(xp, wb.y, acc[3]);
            acc[4] = fma2(xp, wc2.x, acc[4]);
            acc[5] = fma2(xp, wc2.y, acc[5]);
            acc[6] = fma2(xp, wd.x, acc[6]);
            acc[7] = fma2(xp, wd.y, acc[7]);
        }
    }

    // write: lane's row, 16 floats = 4 STG.128, warp-contiguous 2KB
    float4 r0, r1, r2, r3;
    upk2(acc[0], r0.x, r0.y); upk2(acc[1], r0.z, r0.w);
    upk2(acc[2], r1.x, r1.y); upk2(acc[3], r1.z, r1.w);
    upk2(acc[4], r2.x, r2.y); upk2(acc[5], r2.z, r2.w);
    upk2(acc[6], r3.x, r3.y); upk2(acc[7], r3.z, r3.w);
    float4* dst = (float4*)&g_pre[row * 16];
    dst[0] = r0; dst[1] = r1; dst[2] = r2; dst[3] = r3;
}

// ---------------------------------------------------------------------------
// One recurrence step (quad layout + butterfly transpose). Reads P (pre row),
// updates ck (lane-owned c), hown, and the broadcast h0..h3.
// ---------------------------------------------------------------------------
#define QSTEP(P)                                                              \
    {                                                                         \
        u64 z01 = pk2((P).x, (P).y), z23 = pk2((P).z, (P).w);                 \
        u64 hp;                                                               \
        hp = pk2(h0, h0); z01 = fma2(hp, wh2[0][0], z01); z23 = fma2(hp, wh2[0][1], z23); \
        hp = pk2(h1, h1); z01 = fma2(hp, wh2[1][0], z01); z23 = fma2(hp, wh2[1][1], z23); \
        hp = pk2(h2, h2); z01 = fma2(hp, wh2[2][0], z01); z23 = fma2(hp, wh2[2][1], z23); \
        hp = pk2(h3, h3); z01 = fma2(hp, wh2[3][0], z01); z23 = fma2(hp, wh2[3][1], z23); \
        float z0, z1, z2, z3;                                                 \
        upk2(z01, z0, z1);                                                    \
        upk2(z23, z2, z3);                                                    \
        float q0 = __cosf(z0);                                                \
        float q1 = __cosf(z1);                                                \
        float q2 = __cosf(z2);                                                \
        float q3 = __cosf(z3);                                                \
        float m  = q0 * q1;                                                   \
        float r0 = q0;                                                        \
        float r1 = m;                                                         \
        float r2 = m * q2;                                                    \
        float r3 = m * (q2 * q3);                                             \
        {                                                                     \
            float v1 = o1 ? r0 : r1;                                          \
            float u1 = o1 ? r2 : r3;                                          \
            float x1 = __shfl_xor_sync(FULL, v1, 1);                          \
            float y1 = __shfl_xor_sync(FULL, u1, 1);                          \
            r0 = o1 ? x1 : r0;  r1 = o1 ? r1 : x1;                            \
            r2 = o1 ? y1 : r2;  r3 = o1 ? r3 : y1;                            \
            float v2 = o2 ? r0 : r2;                                          \
            float u2 = o2 ? r1 : r3;                                          \
            float x2 = __shfl_xor_sync(FULL, v2, 2);                          \
            float y2 = __shfl_xor_sync(FULL, u2, 2);                          \
            r0 = o2 ? x2 : r0;  r1 = o2 ? y2 : r1;                            \
            r2 = o2 ? r2 : x2;  r3 = o2 ? r3 : y2;                            \
        }                                                                     \
        float f = fmaf(0.5f, tanh_hw(0.5f * r0), 0.5f);                       \
        float i = fmaf(0.5f, tanh_hw(0.5f * r1), 0.5f);                       \
        float u = tanh_hw(r2);                                                \
        float o = fmaf(0.5f, tanh_hw(0.5f * r3), 0.5f);                       \
        ck = fmaf(f, ck, i * u);                                              \
        hown = o * tanh_exp(ck);                                              \
        h0 = __shfl_sync(FULL, hown, base);                                   \
        h1 = __shfl_sync(FULL, hown, base + 1);                               \
        h2 = __shfl_sync(FULL, hown, base + 2);                               \
        h3 = __shfl_sync(FULL, hown, base + 3);                               \
    }

// ---------------------------------------------------------------------------
// Kernel 2: sequence-parallel scan. 512 blocks x 128 threads.
// blockIdx.x = chunk*8 + elem_group. Serial wall = 96 steps.
// Chunks with t0 <= 64 are exact; later chunks burn 64 steps.
// ---------------------------------------------------------------------------
__global__ __launch_bounds__(128) void qlstm_scan(
    const float* __restrict__ W0, const float* __restrict__ W1,
    const float* __restrict__ W2, const float* __restrict__ W3,
    float* __restrict__ out)
{
    const unsigned FULL = 0xffffffffu;
    int warp = (int)threadIdx.x >> 5;
    int lane = (int)threadIdx.x & 31;
    int g    = lane & 3;
    int base = lane & ~3;
    bool o1  = (g & 1) != 0;
    bool o2  = (g & 2) != 0;

    int ci = (int)blockIdx.x >> 3;          // chunk index 0..63
    int eg = (int)blockIdx.x & 7;           // element group 0..7
    int b  = eg * 32 + warp * 8 + (lane >> 2);

    int t0 = ci * CHUNK;
    int tb = t0 - BURN; if (tb < 0) tb = 0;
    int nburn = t0 - tb;                    // 0, 32, or 64 (multiple of 4)

    // recurrent weights for this lane's gate, packed f32x2
    const float* W = (g == 0) ? W0 : (g == 1) ? W1 : (g == 2) ? W2 : W3;
    u64 wh2[4][2];
    #pragma unroll
    for (int j = 0; j < 4; j++) {
        wh2[j][0] = pk2(W[(DD + j) * 4 + 0], W[(DD + j) * 4 + 1]);
        wh2[j][1] = pk2(W[(DD + j) * 4 + 2], W[(DD + j) * 4 + 3]);
    }

    float h0 = 0.f, h1 = 0.f, h2 = 0.f, h3 = 0.f;
    float ck = 0.f;
    float hown = 0.f;

    // 4-deep register prefetch ring over pre[t][b][g*4..g*4+3] (float4/t).
    const float4* pp = (const float4*)g_pre + (size_t)b * 4 + g + (size_t)tb * 1024;
    float4 buf[4];
    buf[0] = pp[0];
    buf[1] = pp[1024];
    buf[2] = pp[2048];
    buf[3] = pp[3072];
    pp += 4096;

    // burn-in: establish (h,c) without storing
    #pragma unroll 4
    for (int t = 0; t < nburn; t++) {
        float4 P = buf[t & 3];
        buf[t & 3] = *pp;
        pp += 1024;
        QSTEP(P)
    }

    // emit CHUNK steps
    float* op = out + (size_t)t0 * (BB * 4) + (size_t)b * 4 + g;
    #pragma unroll 4
    for (int t = 0; t < CHUNK; t++) {
        float4 P = buf[t & 3];
        buf[t & 3] = *pp;       // padded region covers the t0+CHUNK+3 tail
        pp += 1024;
        QSTEP(P)
        *op = hown;             // coalesced STG.32
        op += BB * 4;
    }

    // trailing hx / cx blocks: only the last chunk owns the final state
    if (ci == NCHUNK - 1) {
        out[(size_t)TT * BB * 4 + (size_t)b * 4 + g] = hown;
        out[(size_t)TT * BB * 4 + (size_t)BB * 4 + (size_t)b * 4 + g] = ck;
    }
}

// ---------------------------------------------------------------------------
extern "C" void kernel_launch(void* const* d_in, const int* in_sizes, int n_in,
                              void* d_out, int out_size) {
    const float* x  = (const float*)d_in[0];
    const float* Wf = (const float*)d_in[1];
    const float* bf = (const float*)d_in[2];
    const float* qf = (const float*)d_in[3];
    const float* Wi = (const float*)d_in[4];
    const float* bi = (const float*)d_in[5];
    const float* qi = (const float*)d_in[6];
    const float* Wu = (const float*)d_in[7];
    const float* bu = (const float*)d_in[8];
    const float* qu = (const float*)d_in[9];
    const float* Wo = (const float*)d_in[10];
    const float* bo = (const float*)d_in[11];
    const float* qo = (const float*)d_in[12];

    qlstm_gemm<<<ROWS / 256, 256>>>(x, Wf, bf, qf, Wi, bi, qi, Wu, bu, qu, Wo, bo, qo);
    qlstm_scan<<<NCHUNK * 8, 128>>>(Wf, Wi, Wu, Wo, (float*)d_out);
}